// round 4
// baseline (speedup 1.0000x reference)
#include <cuda_runtime.h>
#include <cstdint>

// Problem constants
#define CIN      32
#define COUT     64
#define OUT_DIM  1024
#define KP       4
#define DLEN     4096            // OUT_DIM * KP
#define BSZ      16
#define P_TILE   8               // patches per CTA
#define NTHREADS 512             // 16 warps
#define STAGES   8               // w pipeline depth (ring in smem)

#define XS_BYTES (BSZ * CIN * P_TILE * KP * 4)        // 64 KB
#define WS_STAGE_BYTES (16 * 512)                     // 8 KB per stage (16 warps x 512B)
#define WS_BYTES (STAGES * WS_STAGE_BYTES)            // 64 KB
#define SMEM_BYTES (XS_BYTES + WS_BYTES)              // 128 KB

// Packed dual-FMA: only reachable via PTX fma.rn.f32x2.
__device__ __forceinline__ unsigned long long ffma2(unsigned long long a,
                                                    unsigned long long b,
                                                    unsigned long long c) {
    unsigned long long d;
    asm("fma.rn.f32x2 %0, %1, %2, %3;" : "=l"(d) : "l"(a), "l"(b), "l"(c));
    return d;
}

__device__ __forceinline__ void cp_async16(uint32_t dst_smem, const void* src) {
    asm volatile("cp.async.cg.shared.global [%0], [%1], 16;\n"
                 :: "r"(dst_smem), "l"(src));
}
__device__ __forceinline__ void cp_commit() {
    asm volatile("cp.async.commit_group;\n" ::);
}
template <int N>
__device__ __forceinline__ void cp_wait() {
    asm volatile("cp.async.wait_group %0;\n" :: "n"(N));
}

__global__ void __launch_bounds__(NTHREADS, 1)
lc1d_kernel(const float* __restrict__ x, const float* __restrict__ w,
            float* __restrict__ out) {
    extern __shared__ char smem[];

    const int tid  = threadIdx.x;
    const int lane = tid & 31;
    const int wid  = tid >> 5;
    const int p0   = blockIdx.x * P_TILE;

    const int p_l = lane & 7;            // patch within tile (8 contiguous)
    const int b0  = (lane >> 3) * 4;     // batch group (4 b's per thread)
    const int o0  = wid * 4;             // 4 output channels per warp

    uint32_t smem_u32;
    asm("{ .reg .u64 t; cvta.to.shared.u64 t, %1; cvt.u32.u64 %0, t; }"
        : "=r"(smem_u32) : "l"(smem));
    const uint32_t xs_u32 = smem_u32;
    const uint32_t ws_u32 = smem_u32 + XS_BYTES;

    // Staging source for this thread's w element: row o0 + (lane>>3), 16B chunk (lane&7)
    const int jw = lane >> 3;            // which of the warp's 4 o-rows this lane stages
    const int uw = lane & 7;             // 16B chunk within the 128B row
    const float* wsrc0 = w + (size_t)(o0 + jw) * (CIN * DLEN) + (p0 + uw) * KP;
    const uint32_t wdst_base = ws_u32 + wid * 512 + jw * 128 + uw * 16;

    // ---- Prologue ----
    // Group 0: all of x (8 x 16B per thread) + w stage 0.
    {
#pragma unroll
        for (int r = 0; r < 8; ++r) {
            int idx = tid + r * NTHREADS;          // 0..4095 float4's
            int q = idx & 7;
            int c = (idx >> 3) & 31;
            int b = idx >> 8;
            cp_async16(xs_u32 + idx * 16,
                       reinterpret_cast<const float4*>(x) + (b * 32768 + c * 1024 + p0 + q));
        }
        cp_async16(wdst_base + 0 * WS_STAGE_BYTES, wsrc0 + 0 * DLEN);
        cp_commit();
    }
    // Groups 1..6: w stages 1..6
#pragma unroll
    for (int s = 1; s < STAGES - 1; ++s) {
        cp_async16(wdst_base + (s & 7) * WS_STAGE_BYTES, wsrc0 + s * DLEN);
        cp_commit();
    }

    cp_wait<STAGES - 2>();     // group 0 complete (x + w stage 0)
    __syncthreads();           // x visible to all warps

    unsigned long long acc[4][4];       // [b][o] packed f32x2
#pragma unroll
    for (int i = 0; i < 4; ++i)
#pragma unroll
        for (int j = 0; j < 4; ++j) acc[i][j] = 0ULL;

    const uint32_t xaddr0 = xs_u32 + (b0 * 1024 + p_l * 4) * 4;   // bytes
    const uint32_t waddr0 = ws_u32 + wid * 512 + p_l * 16;

#pragma unroll
    for (int c = 0; c < CIN; ++c) {
        if (c > 0) {
            cp_wait<STAGES - 2>();     // stage c landed (group-count invariant:
                                       // committed = 7+c, keep newest 6 -> group c done)
            __syncwarp();              // cross-lane visibility of warp-private w region
        }

        const uint32_t wst = waddr0 + (c & 7) * WS_STAGE_BYTES;
        const uint32_t xst = xaddr0 + c * 128;

        // x: [b0+i][c][p_l*4..+4] (LDS.128, phase-contiguous across lane groups)
        ulonglong2 xv[4];
#pragma unroll
        for (int i = 0; i < 4; ++i) {
            asm volatile("ld.shared.v2.u64 {%0, %1}, [%2];"
                         : "=l"(xv[i].x), "=l"(xv[i].y)
                         : "r"(xst + i * 4096));
        }

        // w: warp-private staged rows, broadcast across b lane groups
        ulonglong2 wv[4];
#pragma unroll
        for (int j = 0; j < 4; ++j) {
            asm volatile("ld.shared.v2.u64 {%0, %1}, [%2];"
                         : "=l"(wv[j].x), "=l"(wv[j].y)
                         : "r"(wst + j * 128));
        }

#pragma unroll
        for (int i = 0; i < 4; ++i)
#pragma unroll
            for (int j = 0; j < 4; ++j) {
                acc[i][j] = ffma2(wv[j].x, xv[i].x, acc[i][j]);   // k0,k1
                acc[i][j] = ffma2(wv[j].y, xv[i].y, acc[i][j]);   // k2,k3
            }

        // Refill: stage c+7 into slot (c+7)&7. Commit EVERY iteration (possibly
        // empty) so wait_group<6> always means "stage c complete".
        if (c + (STAGES - 1) < CIN)
            cp_async16(wdst_base + ((c + STAGES - 1) & 7) * WS_STAGE_BYTES,
                       wsrc0 + (c + STAGES - 1) * DLEN);
        cp_commit();
    }

    // ---- Epilogue ----
    const float scale = 0.17677669529663687f;   // 1/sqrt(32)
    const int p = p0 + p_l;
#pragma unroll
    for (int i = 0; i < 4; ++i)
#pragma unroll
        for (int j = 0; j < 4; ++j) {
            float2 v = *reinterpret_cast<float2*>(&acc[i][j]);
            out[(b0 + i) * (COUT * OUT_DIM) + (o0 + j) * OUT_DIM + p] =
                (v.x + v.y) * scale;
        }
}

extern "C" void kernel_launch(void* const* d_in, const int* in_sizes, int n_in,
                              void* d_out, int out_size) {
    const float* x = (const float*)d_in[0];
    const float* w = (const float*)d_in[1];
    float* out = (float*)d_out;

    cudaFuncSetAttribute(lc1d_kernel, cudaFuncAttributeMaxDynamicSharedMemorySize,
                         SMEM_BYTES);

    lc1d_kernel<<<OUT_DIM / P_TILE, NTHREADS, SMEM_BYTES>>>(x, w, out);
}

// round 5
// speedup vs baseline: 1.0154x; 1.0154x over previous
#include <cuda_runtime.h>
#include <cstdint>

// Problem constants
#define CIN      32
#define COUT     64
#define OUT_DIM  1024
#define KP       4
#define DLEN     4096            // OUT_DIM * KP
#define BSZ      16
#define P_TILE   8               // patches per CTA
#define NTHREADS 256             // 8 warps, each owns 8 output channels
#define STAGES   8               // w pipeline depth (ring in smem)

#define XS_BYTES (BSZ * CIN * P_TILE * KP * 4)        // 64 KB
#define WS_STAGE_BYTES (8 * 1024)                     // 8 KB/stage (8 warps x 1KB)
#define WS_BYTES (STAGES * WS_STAGE_BYTES)            // 64 KB
#define SMEM_BYTES (XS_BYTES + WS_BYTES)              // 128 KB

// Packed dual-FMA: only reachable via PTX fma.rn.f32x2.
__device__ __forceinline__ unsigned long long ffma2(unsigned long long a,
                                                    unsigned long long b,
                                                    unsigned long long c) {
    unsigned long long d;
    asm("fma.rn.f32x2 %0, %1, %2, %3;" : "=l"(d) : "l"(a), "l"(b), "l"(c));
    return d;
}

__device__ __forceinline__ void cp_async16(uint32_t dst_smem, const void* src) {
    asm volatile("cp.async.cg.shared.global [%0], [%1], 16;\n"
                 :: "r"(dst_smem), "l"(src));
}
__device__ __forceinline__ void cp_commit() {
    asm volatile("cp.async.commit_group;\n" ::);
}
template <int N>
__device__ __forceinline__ void cp_wait() {
    asm volatile("cp.async.wait_group %0;\n" :: "n"(N));
}

__global__ void __launch_bounds__(NTHREADS, 1)
lc1d_kernel(const float* __restrict__ x, const float* __restrict__ w,
            float* __restrict__ out) {
    extern __shared__ char smem[];

    const int tid  = threadIdx.x;
    const int lane = tid & 31;
    const int wid  = tid >> 5;           // 0..7
    const int p0   = blockIdx.x * P_TILE;

    const int p_l = lane & 7;            // patch within tile
    const int bg  = lane >> 3;           // 4 batch groups
    const int b0  = bg * 4;              // thread covers b0..b0+3
    const int o0  = wid * 8;             // warp covers 8 output channels

    uint32_t smem_u32;
    asm("{ .reg .u64 t; cvta.to.shared.u64 t, %1; cvt.u32.u64 %0, t; }"
        : "=r"(smem_u32) : "l"(smem));
    const uint32_t xs_u32 = smem_u32;
    const uint32_t ws_u32 = smem_u32 + XS_BYTES;

    // ---- w staging map: warp stages its 8 o-rows (1KB/stage).
    // 64 16B-units per warp-stage; lane stages units {lane, lane+32}:
    //   row = lane>>3 and (lane>>3)+4, chunk = lane&7.
    const int rw = lane >> 3;            // staged row A (row B = rw+4)
    const int uw = lane & 7;             // 16B chunk within 128B row
    const float* wsrcA = w + (size_t)(o0 + rw) * (CIN * DLEN) + (p0 + uw) * KP;
    const float* wsrcB = wsrcA + (size_t)4 * (CIN * DLEN);
    const uint32_t wdstA = ws_u32 + wid * 1024 + rw * 128 + uw * 16;
    const uint32_t wdstB = wdstA + 4 * 128;

    // ---- Prologue ----
    // Group 0: all of x (16 x 16B per thread) + w stage 0.
    {
#pragma unroll
        for (int r = 0; r < 16; ++r) {
            int idx = tid + r * NTHREADS;          // 0..4095 float4's
            int q = idx & 7;
            int c = (idx >> 3) & 31;
            int b = idx >> 8;
            cp_async16(xs_u32 + idx * 16,
                       reinterpret_cast<const float4*>(x) + (b * 32768 + c * 1024 + p0 + q));
        }
        cp_async16(wdstA, wsrcA);
        cp_async16(wdstB, wsrcB);
        cp_commit();
    }
    // Groups 1..6: w stages 1..6
#pragma unroll
    for (int s = 1; s < STAGES - 1; ++s) {
        cp_async16(wdstA + (s & 7) * WS_STAGE_BYTES, wsrcA + s * DLEN);
        cp_async16(wdstB + (s & 7) * WS_STAGE_BYTES, wsrcB + s * DLEN);
        cp_commit();
    }

    cp_wait<STAGES - 2>();     // group 0 complete (x + w stage 0)
    __syncthreads();           // x visible to all warps

    unsigned long long acc[4][8];       // [b][o] packed f32x2
#pragma unroll
    for (int i = 0; i < 4; ++i)
#pragma unroll
        for (int j = 0; j < 8; ++j) acc[i][j] = 0ULL;

    const uint32_t xaddr0 = xs_u32 + (b0 * 1024 + p_l * 4) * 4;   // bytes
    const uint32_t waddr0 = ws_u32 + wid * 1024 + p_l * 16;

#pragma unroll
    for (int c = 0; c < CIN; ++c) {
        if (c > 0) {
            cp_wait<STAGES - 2>();     // committed = 7+c, keep newest 6 -> group c done
            __syncwarp();              // cross-lane visibility of warp's staged w
        }

        const uint32_t wst = waddr0 + (c & 7) * WS_STAGE_BYTES;
        const uint32_t xst = xaddr0 + c * 128;

        // x: [b0+i][c][p_l*4..+4] (LDS.128, phase = lane-group -> conflict-free)
        ulonglong2 xv[4];
#pragma unroll
        for (int i = 0; i < 4; ++i) {
            asm volatile("ld.shared.v2.u64 {%0, %1}, [%2];"
                         : "=l"(xv[i].x), "=l"(xv[i].y)
                         : "r"(xst + i * 4096));
        }

        // w: warp's 8 staged rows, broadcast across the 4 b lane-groups
        ulonglong2 wv[8];
#pragma unroll
        for (int j = 0; j < 8; ++j) {
            asm volatile("ld.shared.v2.u64 {%0, %1}, [%2];"
                         : "=l"(wv[j].x), "=l"(wv[j].y)
                         : "r"(wst + j * 128));
        }

#pragma unroll
        for (int i = 0; i < 4; ++i)
#pragma unroll
            for (int j = 0; j < 8; ++j) {
                acc[i][j] = ffma2(wv[j].x, xv[i].x, acc[i][j]);   // k0,k1
                acc[i][j] = ffma2(wv[j].y, xv[i].y, acc[i][j]);   // k2,k3
            }

        // Refill stage c+7 into slot (c+7)&7. Commit EVERY iteration (possibly
        // empty) so wait_group<6> always means "stage c complete".
        if (c + (STAGES - 1) < CIN) {
            cp_async16(wdstA + ((c + STAGES - 1) & 7) * WS_STAGE_BYTES,
                       wsrcA + (c + STAGES - 1) * DLEN);
            cp_async16(wdstB + ((c + STAGES - 1) & 7) * WS_STAGE_BYTES,
                       wsrcB + (c + STAGES - 1) * DLEN);
        }
        cp_commit();
    }

    // ---- Epilogue ----
    const float scale = 0.17677669529663687f;   // 1/sqrt(32)
    const int p = p0 + p_l;
#pragma unroll
    for (int i = 0; i < 4; ++i)
#pragma unroll
        for (int j = 0; j < 8; ++j) {
            float2 v = *reinterpret_cast<float2*>(&acc[i][j]);
            out[(b0 + i) * (COUT * OUT_DIM) + (o0 + j) * OUT_DIM + p] =
                (v.x + v.y) * scale;
        }
}

extern "C" void kernel_launch(void* const* d_in, const int* in_sizes, int n_in,
                              void* d_out, int out_size) {
    const float* x = (const float*)d_in[0];
    const float* w = (const float*)d_in[1];
    float* out = (float*)d_out;

    cudaFuncSetAttribute(lc1d_kernel, cudaFuncAttributeMaxDynamicSharedMemorySize,
                         SMEM_BYTES);

    lc1d_kernel<<<OUT_DIM / P_TILE, NTHREADS, SMEM_BYTES>>>(x, w, out);
}